// round 1
// baseline (speedup 1.0000x reference)
#include <cuda_runtime.h>
#include <math.h>
#include <stdint.h>

#define NMAX   (1 << 19)
#define TBL    (1 << 19)
#define TMASK  (TBL - 1)

// scratch: per-sample {r, g, b, s}
__device__ float4 g_samp[NMAX];

struct ResTable { float r[16]; };

// ---------------------------------------------------------------------------
// Kernel A: per-sample hash encode + MLPs -> (rgb, s=sigma*dt)
// ---------------------------------------------------------------------------
__global__ __launch_bounds__(128)
void sample_kernel(
    const float* __restrict__ ts, const float* __restrict__ te,
    const float* __restrict__ ro, const float* __restrict__ rd,
    const int*   __restrict__ ridx,
    const float* __restrict__ tables,
    const float* __restrict__ w0,  const float* __restrict__ w1,
    const float* __restrict__ hw0, const float* __restrict__ hw1,
    const float* __restrict__ hw2, const float* __restrict__ aabb,
    ResTable res, int N)
{
    __shared__ float sw[9344];
    float* s_w0 = sw;          // [32][64]  2048
    float* s_w1 = sw + 2048;   // [64][16]  1024
    float* s_h0 = sw + 3072;   // [31][64]  1984
    float* s_h1 = sw + 5056;   // [64][64]  4096
    float* s_h2 = sw + 9152;   // [64][3]    192

    for (int i = threadIdx.x; i < 2048; i += 128) s_w0[i] = w0[i];
    for (int i = threadIdx.x; i < 1024; i += 128) s_w1[i] = w1[i];
    for (int i = threadIdx.x; i < 1984; i += 128) s_h0[i] = hw0[i];
    for (int i = threadIdx.x; i < 4096; i += 128) s_h1[i] = hw1[i];
    for (int i = threadIdx.x; i <  192; i += 128) s_h2[i] = hw2[i];
    __syncthreads();

    int i = blockIdx.x * 128 + threadIdx.x;
    if (i >= N) return;

    int r = ridx[i];
    float t0 = ts[i], t1 = te[i];
    float tmid = (t0 + t1) * 0.5f;

    float ox = ro[3 * r + 0], oy = ro[3 * r + 1], oz = ro[3 * r + 2];
    float dx = rd[3 * r + 0], dy = rd[3 * r + 1], dz = rd[3 * r + 2];

    float a0 = aabb[0], a1 = aabb[1], a2 = aabb[2];
    float a3 = aabb[3], a4 = aabb[4], a5 = aabb[5];

    float px_ = ox + dx * tmid;
    float py_ = oy + dy * tmid;
    float pz_ = oz + dz * tmid;

    float xn0 = (px_ - a0) / (a3 - a0 + 1e-5f);
    float xn1 = (py_ - a1) / (a4 - a1 + 1e-5f);
    float xn2 = (pz_ - a2) / (a5 - a2 + 1e-5f);

    bool sel = (xn0 > 0.f) && (xn0 < 1.f) &&
               (xn1 > 0.f) && (xn1 < 1.f) &&
               (xn2 > 0.f) && (xn2 < 1.f);

    float xc0 = fminf(fmaxf(xn0, 0.f), 1.f);
    float xc1 = fminf(fmaxf(xn1, 0.f), 1.f);
    float xc2 = fminf(fmaxf(xn2, 0.f), 1.f);

    // ---------------- hash encode: 16 levels -> enc[32] ----------------
    float enc[32];
    const float2* __restrict__ tb = (const float2*)tables;
#pragma unroll
    for (int l = 0; l < 16; l++) {
        float rs = res.r[l];
        float px = xc0 * rs, py = xc1 * rs, pz = xc2 * rs;
        float p0x = floorf(px), p0y = floorf(py), p0z = floorf(pz);
        float fx = px - p0x, fy = py - p0y, fz = pz - p0z;
        unsigned ux = (unsigned)p0x, uy = (unsigned)p0y, uz = (unsigned)p0z;
        unsigned hx0 = ux,                  hx1 = ux + 1u;
        unsigned hy0 = uy * 2654435761u,    hy1 = (uy + 1u) * 2654435761u;
        unsigned hz0 = uz * 805459861u,     hz1 = (uz + 1u) * 805459861u;
        float wx0 = 1.f - fx, wx1 = fx;
        float wy0 = 1.f - fy, wy1 = fy;
        float wz0 = 1.f - fz, wz1 = fz;
        const float2* __restrict__ t = tb + (size_t)l * TBL;
        float f0 = 0.f, f1 = 0.f;
#pragma unroll
        for (int c = 0; c < 8; c++) {
            unsigned h = ((c & 4) ? hx1 : hx0) ^ ((c & 2) ? hy1 : hy0) ^ ((c & 1) ? hz1 : hz0);
            h &= TMASK;
            float w = ((c & 4) ? wx1 : wx0) * ((c & 2) ? wy1 : wy0) * ((c & 1) ? wz1 : wz0);
            float2 v = __ldg(t + h);
            f0 = fmaf(v.x, w, f0);
            f1 = fmaf(v.y, w, f1);
        }
        enc[2 * l]     = f0;
        enc[2 * l + 1] = f1;
    }

    // ---------------- base MLP: 32 -> 64 (relu) -> 16 ----------------
    float h1[64];
#pragma unroll
    for (int j = 0; j < 64; j++) h1[j] = 0.f;
#pragma unroll
    for (int k = 0; k < 32; k++) {
        float e = enc[k];
#pragma unroll
        for (int j = 0; j < 64; j++) h1[j] = fmaf(e, s_w0[k * 64 + j], h1[j]);
    }
#pragma unroll
    for (int j = 0; j < 64; j++) h1[j] = fmaxf(h1[j], 0.f);

    float h2[16];
#pragma unroll
    for (int k = 0; k < 16; k++) h2[k] = 0.f;
#pragma unroll
    for (int j = 0; j < 64; j++) {
        float v = h1[j];
#pragma unroll
        for (int k = 0; k < 16; k++) h2[k] = fmaf(v, s_w1[j * 16 + k], h2[k]);
    }

    float sigma = sel ? expf(h2[0] - 1.f) : 0.f;
    float s = sigma * (t1 - t0);

    // ---------------- SH deg 4 on direction ----------------
    float x = dx, y = dy, z = dz;
    float x2 = x * x, y2 = y * y, z2 = z * z;
    float xy = x * y, yz = y * z, xz = x * z;

    float hh[31];
    hh[0]  = 0.28209479177387814f;
    hh[1]  = -0.48860251190291987f * y;
    hh[2]  =  0.48860251190291987f * z;
    hh[3]  = -0.48860251190291987f * x;
    hh[4]  =  1.0925484305920792f * xy;
    hh[5]  = -1.0925484305920792f * yz;
    hh[6]  =  0.94617469575756f * z2 - 0.31539156525252005f;
    hh[7]  = -1.0925484305920792f * xz;
    hh[8]  =  0.5462742152960396f * (x2 - y2);
    hh[9]  = -0.5900435899266435f * y * (3.f * x2 - y2);
    hh[10] =  2.890611442640554f * xy * z;
    hh[11] = -0.4570457994644658f * y * (4.f * z2 - x2 - y2);
    hh[12] =  0.3731763325901154f * z * (2.f * z2 - 3.f * x2 - 3.f * y2);
    hh[13] = -0.4570457994644658f * x * (4.f * z2 - x2 - y2);
    hh[14] =  1.445305721320277f * z * (x2 - y2);
    hh[15] = -0.5900435899266435f * x * (x2 - 3.f * y2);
#pragma unroll
    for (int k = 0; k < 15; k++) hh[16 + k] = h2[1 + k];

    // ---------------- head MLP: 31 -> 64 (relu) -> 64 (relu) -> 3 (sigmoid) --
    float ha[64];
#pragma unroll
    for (int j = 0; j < 64; j++) ha[j] = 0.f;
#pragma unroll
    for (int k = 0; k < 31; k++) {
        float v = hh[k];
#pragma unroll
        for (int j = 0; j < 64; j++) ha[j] = fmaf(v, s_h0[k * 64 + j], ha[j]);
    }
#pragma unroll
    for (int j = 0; j < 64; j++) ha[j] = fmaxf(ha[j], 0.f);

    float hb[64];
#pragma unroll
    for (int j = 0; j < 64; j++) hb[j] = 0.f;
#pragma unroll
    for (int k = 0; k < 64; k++) {
        float v = ha[k];
#pragma unroll
        for (int j = 0; j < 64; j++) hb[j] = fmaf(v, s_h1[k * 64 + j], hb[j]);
    }
#pragma unroll
    for (int j = 0; j < 64; j++) hb[j] = fmaxf(hb[j], 0.f);

    float c0 = 0.f, c1 = 0.f, c2 = 0.f;
#pragma unroll
    for (int j = 0; j < 64; j++) {
        float v = hb[j];
        c0 = fmaf(v, s_h2[j * 3 + 0], c0);
        c1 = fmaf(v, s_h2[j * 3 + 1], c1);
        c2 = fmaf(v, s_h2[j * 3 + 2], c2);
    }
    float rr = 1.f / (1.f + expf(-c0));
    float gg = 1.f / (1.f + expf(-c1));
    float bb = 1.f / (1.f + expf(-c2));

    g_samp[i] = make_float4(rr, gg, bb, s);
}

// ---------------------------------------------------------------------------
// Kernel B: warp per ray — scan of s, transmittance, weighted accumulation
// ---------------------------------------------------------------------------
__global__ __launch_bounds__(256)
void accum_kernel(const float* __restrict__ ts, const float* __restrict__ te,
                  const int* __restrict__ ridx, float* __restrict__ out,
                  int N, int R)
{
    const unsigned FULL = 0xFFFFFFFFu;
    int warp = (blockIdx.x * blockDim.x + threadIdx.x) >> 5;
    int lane = threadIdx.x & 31;
    if (warp >= R) return;
    int r = warp;

    // lower_bound(r)
    int lo = 0, hi = N;
    while (lo < hi) { int m = (lo + hi) >> 1; if (ridx[m] < r) lo = m + 1; else hi = m; }
    int start = lo;
    // lower_bound(r+1)
    hi = N;
    while (lo < hi) { int m = (lo + hi) >> 1; if (ridx[m] < r + 1) lo = m + 1; else hi = m; }
    int end = lo;

    float carry = 0.f;
    float cr = 0.f, cg = 0.f, cb = 0.f, cw = 0.f, cd = 0.f;

    for (int base = start; base < end; base += 32) {
        int i = base + lane;
        bool v = i < end;
        float4 q = v ? g_samp[i] : make_float4(0.f, 0.f, 0.f, 0.f);
        float si = q.w;
        float tm = 0.f;
        if (v) tm = 0.5f * (ts[i] + te[i]);

        // inclusive warp scan of si
        float incl = si;
#pragma unroll
        for (int off = 1; off < 32; off <<= 1) {
            float t = __shfl_up_sync(FULL, incl, off);
            if (lane >= off) incl += t;
        }
        float excl  = carry + (incl - si);
        float trans = expf(-excl);
        float alpha = 1.f - expf(-si);
        float w = trans * alpha;           // invalid lanes: si=0 -> alpha=0 -> w=0

        cr += w * q.x;
        cg += w * q.y;
        cb += w * q.z;
        cw += w;
        cd += w * tm;

        carry += __shfl_sync(FULL, incl, 31);
    }

    // warp reduction
#pragma unroll
    for (int off = 16; off >= 1; off >>= 1) {
        cr += __shfl_xor_sync(FULL, cr, off);
        cg += __shfl_xor_sync(FULL, cg, off);
        cb += __shfl_xor_sync(FULL, cb, off);
        cw += __shfl_xor_sync(FULL, cw, off);
        cd += __shfl_xor_sync(FULL, cd, off);
    }

    if (lane == 0) {
        out[3 * r + 0] = cr;
        out[3 * r + 1] = cg;
        out[3 * r + 2] = cb;
        out[3 * R + r] = cw;                                    // opacity
        out[4 * R + r] = cd / fmaxf(cw, 1.1920929e-7f);         // depth
    }
}

// ---------------------------------------------------------------------------
extern "C" void kernel_launch(void* const* d_in, const int* in_sizes, int n_in,
                              void* d_out, int out_size)
{
    const float* ts     = (const float*)d_in[0];
    const float* te     = (const float*)d_in[1];
    const float* ro     = (const float*)d_in[2];
    const float* rd     = (const float*)d_in[3];
    const int*   ridx   = (const int*)  d_in[4];
    const float* tables = (const float*)d_in[5];
    const float* w0     = (const float*)d_in[6];
    const float* w1     = (const float*)d_in[7];
    const float* hw0    = (const float*)d_in[8];
    const float* hw1    = (const float*)d_in[9];
    const float* hw2    = (const float*)d_in[10];
    const float* aabb   = (const float*)d_in[11];
    float* out = (float*)d_out;

    int N = in_sizes[0];
    int R = in_sizes[2] / 3;

    // resolutions, computed in double to match numpy exactly
    ResTable res;
    double scale = exp((log(4096.0) - log(16.0)) / 15.0);
    double acc = 16.0;
    for (int l = 0; l < 16; l++) {
        res.r[l] = (float)floor(acc);
        acc *= scale;
    }

    int blocksA = (N + 127) / 128;
    sample_kernel<<<blocksA, 128>>>(ts, te, ro, rd, ridx, tables,
                                    w0, w1, hw0, hw1, hw2, aabb, res, N);

    int warps = R;
    int blocksB = (warps * 32 + 255) / 256;
    accum_kernel<<<blocksB, 256>>>(ts, te, ridx, out, N, R);
}

// round 4
// speedup vs baseline: 1.3957x; 1.3957x over previous
#include <cuda_runtime.h>
#include <math.h>
#include <stdint.h>

#define NMAX   (1 << 19)
#define TBL    (1 << 19)
#define TMASK  (TBL - 1)

// ---------------- global scratch (static, allocation-guard safe) ----------
__device__ float  g_enc[NMAX * 32];    // per-sample hash features (fp32)
__device__ float  g_sh [NMAX * 16];    // per-sample SH deg4       (fp32)
__device__ float  g_dts[NMAX];         // (t1-t0) * selector
__device__ float4 g_samp[NMAX];        // {r,g,b,s}

// weights: base = single tf32; head = hi/lo tf32 pair (3xTF32)
__device__ unsigned g_w0    [32 * 64];
__device__ unsigned g_w1    [64 * 16];
__device__ unsigned g_hw0_hi[32 * 64];
__device__ unsigned g_hw0_lo[32 * 64];
__device__ unsigned g_hw1_hi[64 * 64];
__device__ unsigned g_hw1_lo[64 * 64];
__device__ unsigned g_hw2_hi[64 *  8];
__device__ unsigned g_hw2_lo[64 *  8];

struct ResTable { float r[16]; };

__device__ __forceinline__ unsigned f2tf(float x) {
    unsigned r;
    asm("cvt.rna.tf32.f32 %0, %1;" : "=r"(r) : "f"(x));
    return r;
}

// ---------------------------------------------------------------------------
// weight prep: fp32 -> tf32 (base) / hi+lo tf32 (head), with zero padding
// ---------------------------------------------------------------------------
__global__ void prep_kernel(const float* __restrict__ w0, const float* __restrict__ w1,
                            const float* __restrict__ hw0, const float* __restrict__ hw1,
                            const float* __restrict__ hw2)
{
    int i = blockIdx.x * 256 + threadIdx.x;   // 0..4095
    if (i < 2048) g_w0[i] = f2tf(w0[i]);
    if (i < 1024) g_w1[i] = f2tf(w1[i]);
    if (i < 2048) {
        float v = (i < 1984) ? hw0[i] : 0.f;           // pad k-row 31
        unsigned hi = f2tf(v);
        g_hw0_hi[i] = hi;
        g_hw0_lo[i] = f2tf(v - __uint_as_float(hi));
    }
    if (i < 4096) {
        float v = hw1[i];
        unsigned hi = f2tf(v);
        g_hw1_hi[i] = hi;
        g_hw1_lo[i] = f2tf(v - __uint_as_float(hi));
    }
    if (i < 512) {
        int r = i >> 3, c = i & 7;
        float v = (c < 3) ? hw2[r * 3 + c] : 0.f;      // pad n-cols 3..7
        unsigned hi = f2tf(v);
        g_hw2_hi[i] = hi;
        g_hw2_lo[i] = f2tf(v - __uint_as_float(hi));
    }
}

// ---------------------------------------------------------------------------
// Kernel A: hash encode + SH + dt*selector  (gather-bound, high occupancy)
// ---------------------------------------------------------------------------
__global__ __launch_bounds__(256)
void hash_kernel(
    const float* __restrict__ ts, const float* __restrict__ te,
    const float* __restrict__ ro, const float* __restrict__ rd,
    const int*   __restrict__ ridx,
    const float* __restrict__ tables,
    const float* __restrict__ aabb,
    ResTable res, int N)
{
    int i = blockIdx.x * 256 + threadIdx.x;
    if (i >= N) return;

    int r = ridx[i];
    float t0 = ts[i], t1 = te[i];
    float tmid = (t0 + t1) * 0.5f;

    float ox = ro[3 * r + 0], oy = ro[3 * r + 1], oz = ro[3 * r + 2];
    float dx = rd[3 * r + 0], dy = rd[3 * r + 1], dz = rd[3 * r + 2];

    float a0 = aabb[0], a1 = aabb[1], a2 = aabb[2];
    float a3 = aabb[3], a4 = aabb[4], a5 = aabb[5];

    float xn0 = (ox + dx * tmid - a0) / (a3 - a0 + 1e-5f);
    float xn1 = (oy + dy * tmid - a1) / (a4 - a1 + 1e-5f);
    float xn2 = (oz + dz * tmid - a2) / (a5 - a2 + 1e-5f);

    bool sel = (xn0 > 0.f) && (xn0 < 1.f) &&
               (xn1 > 0.f) && (xn1 < 1.f) &&
               (xn2 > 0.f) && (xn2 < 1.f);
    g_dts[i] = sel ? (t1 - t0) : 0.f;

    float xc0 = fminf(fmaxf(xn0, 0.f), 1.f);
    float xc1 = fminf(fmaxf(xn1, 0.f), 1.f);
    float xc2 = fminf(fmaxf(xn2, 0.f), 1.f);

    const float2* __restrict__ tb = (const float2*)tables;
    float* __restrict__ erow = g_enc + (size_t)i * 32;

#pragma unroll
    for (int l = 0; l < 16; l++) {
        float rs = res.r[l];
        float px = xc0 * rs, py = xc1 * rs, pz = xc2 * rs;
        float p0x = floorf(px), p0y = floorf(py), p0z = floorf(pz);
        float fx = px - p0x, fy = py - p0y, fz = pz - p0z;
        unsigned ux = (unsigned)p0x, uy = (unsigned)p0y, uz = (unsigned)p0z;
        unsigned hx0 = ux,               hx1 = ux + 1u;
        unsigned hy0 = uy * 2654435761u, hy1 = (uy + 1u) * 2654435761u;
        unsigned hz0 = uz * 805459861u,  hz1 = (uz + 1u) * 805459861u;
        float wx0 = 1.f - fx, wy0 = 1.f - fy, wz0 = 1.f - fz;
        const float2* __restrict__ t = tb + (size_t)l * TBL;
        float f0 = 0.f, f1 = 0.f;
#pragma unroll
        for (int c = 0; c < 8; c++) {
            unsigned h = ((c & 4) ? hx1 : hx0) ^ ((c & 2) ? hy1 : hy0) ^ ((c & 1) ? hz1 : hz0);
            h &= TMASK;
            float w = ((c & 4) ? fx : wx0) * ((c & 2) ? fy : wy0) * ((c & 1) ? fz : wz0);
            float2 v = __ldg(t + h);
            f0 = fmaf(v.x, w, f0);
            f1 = fmaf(v.y, w, f1);
        }
        erow[2 * l]     = f0;
        erow[2 * l + 1] = f1;
    }

    // SH deg 4
    float x = dx, y = dy, z = dz;
    float x2 = x * x, y2 = y * y, z2 = z * z;
    float xy = x * y, yz = y * z, xz = x * z;
    float sh[16];
    sh[0]  = 0.28209479177387814f;
    sh[1]  = -0.48860251190291987f * y;
    sh[2]  =  0.48860251190291987f * z;
    sh[3]  = -0.48860251190291987f * x;
    sh[4]  =  1.0925484305920792f * xy;
    sh[5]  = -1.0925484305920792f * yz;
    sh[6]  =  0.94617469575756f * z2 - 0.31539156525252005f;
    sh[7]  = -1.0925484305920792f * xz;
    sh[8]  =  0.5462742152960396f * (x2 - y2);
    sh[9]  = -0.5900435899266435f * y * (3.f * x2 - y2);
    sh[10] =  2.890611442640554f * xy * z;
    sh[11] = -0.4570457994644658f * y * (4.f * z2 - x2 - y2);
    sh[12] =  0.3731763325901154f * z * (2.f * z2 - 3.f * x2 - 3.f * y2);
    sh[13] = -0.4570457994644658f * x * (4.f * z2 - x2 - y2);
    sh[14] =  1.445305721320277f * z * (x2 - y2);
    sh[15] = -0.5900435899266435f * x * (x2 - 3.f * y2);
    float* __restrict__ srow = g_sh + (size_t)i * 16;
#pragma unroll
    for (int k = 0; k < 16; k++) srow[k] = sh[k];
}

// ---------------------------------------------------------------------------
// warp-level tf32 GEMM building block (mma.m16n8k8)
// each warp owns 32 sample rows through the whole MLP chain
// ---------------------------------------------------------------------------
__device__ __forceinline__ void mma8(float c[4], const unsigned a[4],
                                     unsigned b0, unsigned b1)
{
    asm volatile(
        "mma.sync.aligned.m16n8k8.row.col.f32.tf32.tf32.f32 "
        "{%0,%1,%2,%3}, {%4,%5,%6,%7}, {%8,%9}, {%0,%1,%2,%3};"
        : "+f"(c[0]), "+f"(c[1]), "+f"(c[2]), "+f"(c[3])
        : "r"(a[0]), "r"(a[1]), "r"(a[2]), "r"(a[3]), "r"(b0), "r"(b1));
}

// SPLIT=false: single tf32 (A converted rna at load, W pre-converted)
// SPLIT=true : 3xTF32 — acc += Ahi*Bhi + Alo*Bhi + Ahi*Blo
template <int K, int NOUT, int SIN, int SOUT, bool RELU, bool SPLIT>
__device__ __forceinline__ void warp_gemm(const float* __restrict__ sIn,
                                          float* __restrict__ sOut,
                                          const unsigned* __restrict__ Whi,
                                          const unsigned* __restrict__ Wlo,
                                          int warpRow, int lane)
{
    const int g = lane >> 2, c = lane & 3;
#pragma unroll
    for (int mi = 0; mi < 2; mi++) {
        const int r0 = warpRow + mi * 16;
        unsigned ahi[K / 8][4];
        unsigned alo[K / 8][4];
#pragma unroll
        for (int ki = 0; ki < K / 8; ki++) {
            float f0 = sIn[(r0 + g    ) * SIN + ki * 8 + c];
            float f1 = sIn[(r0 + g + 8) * SIN + ki * 8 + c];
            float f2 = sIn[(r0 + g    ) * SIN + ki * 8 + c + 4];
            float f3 = sIn[(r0 + g + 8) * SIN + ki * 8 + c + 4];
            ahi[ki][0] = f2tf(f0);
            ahi[ki][1] = f2tf(f1);
            ahi[ki][2] = f2tf(f2);
            ahi[ki][3] = f2tf(f3);
            if (SPLIT) {
                alo[ki][0] = f2tf(f0 - __uint_as_float(ahi[ki][0]));
                alo[ki][1] = f2tf(f1 - __uint_as_float(ahi[ki][1]));
                alo[ki][2] = f2tf(f2 - __uint_as_float(ahi[ki][2]));
                alo[ki][3] = f2tf(f3 - __uint_as_float(ahi[ki][3]));
            }
        }
#pragma unroll
        for (int ni = 0; ni < NOUT / 8; ni++) {
            float acc[4] = {0.f, 0.f, 0.f, 0.f};
#pragma unroll
            for (int ki = 0; ki < K / 8; ki++) {
                unsigned bh0 = __ldg(Whi + (ki * 8 + c    ) * NOUT + ni * 8 + g);
                unsigned bh1 = __ldg(Whi + (ki * 8 + c + 4) * NOUT + ni * 8 + g);
                mma8(acc, ahi[ki], bh0, bh1);
                if (SPLIT) {
                    mma8(acc, alo[ki], bh0, bh1);
                    unsigned bl0 = __ldg(Wlo + (ki * 8 + c    ) * NOUT + ni * 8 + g);
                    unsigned bl1 = __ldg(Wlo + (ki * 8 + c + 4) * NOUT + ni * 8 + g);
                    mma8(acc, ahi[ki], bl0, bl1);
                }
            }
            float v0 = RELU ? fmaxf(acc[0], 0.f) : acc[0];
            float v1 = RELU ? fmaxf(acc[1], 0.f) : acc[1];
            float v2 = RELU ? fmaxf(acc[2], 0.f) : acc[2];
            float v3 = RELU ? fmaxf(acc[3], 0.f) : acc[3];
            float* o0 = sOut + (r0 + g    ) * SOUT + ni * 8 + 2 * c;
            float* o1 = sOut + (r0 + g + 8) * SOUT + ni * 8 + 2 * c;
            o0[0] = v0; o0[1] = v1;
            o1[0] = v2; o1[1] = v3;
        }
    }
}

// ---------------------------------------------------------------------------
// Kernel B: MLP chain on tensor cores, 128 samples / block, 4 warps
// smem: sA (stride 36) | sX1 (stride 68) | sH2 (stride 20) | sX3 (stride 68)
// ---------------------------------------------------------------------------
__global__ __launch_bounds__(128)
void mlp_kernel(int N)
{
    extern __shared__ float sm[];
    float* sA  = sm;                 // 128*36 = 4608   (A0 -> A1 -> X4[stride 12])
    float* sX1 = sm + 4608;          // 128*68 = 8704   (X1 -> X2)
    float* sH2 = sm + 13312;         // 128*20 = 2560
    float* sX3 = sm + 15872;         // 128*68 = 8704

    const int lane = threadIdx.x & 31;
    const int w = threadIdx.x >> 5;
    const int warpRow = w * 32;
    const int base = blockIdx.x * 128;

    // load A0 (hash features), warp-local, coalesced float4
    {
        const float4* ev = (const float4*)g_enc;
        for (int t = lane; t < 256; t += 32) {
            int r = warpRow + (t >> 3);
            int gi = base + r;
            float4 v = (gi < N) ? ev[(size_t)base * 8 + (size_t)warpRow * 8 + t]
                                : make_float4(0.f, 0.f, 0.f, 0.f);
            float* dst = sA + r * 36 + (t & 7) * 4;
            dst[0] = v.x; dst[1] = v.y; dst[2] = v.z; dst[3] = v.w;
        }
    }
    __syncwarp();

    warp_gemm<32, 64, 36, 68, true,  false>(sA,  sX1, g_w0, nullptr, warpRow, lane); // X1
    __syncwarp();
    warp_gemm<64, 16, 68, 20, false, false>(sX1, sH2, g_w1, nullptr, warpRow, lane); // H2
    __syncwarp();

    // build A1 = [SH(16) | H2[1..15] | 0]
    {
        const float4* sv = (const float4*)g_sh;
        for (int t = lane; t < 128; t += 32) {
            int r = warpRow + (t >> 2);
            int gi = base + r;
            float4 v = (gi < N) ? sv[(size_t)base * 4 + (size_t)warpRow * 4 + t]
                                : make_float4(0.f, 0.f, 0.f, 0.f);
            float* dst = sA + r * 36 + (t & 3) * 4;
            dst[0] = v.x; dst[1] = v.y; dst[2] = v.z; dst[3] = v.w;
        }
        __syncwarp();
        int r = warpRow + lane;
        float* arow = sA + r * 36;
        const float* hrow = sH2 + r * 20;
#pragma unroll
        for (int k = 1; k < 16; k++) arow[15 + k] = hrow[k];
        arow[31] = 0.f;
    }
    __syncwarp();

    warp_gemm<32, 64, 36, 68, true,  true >(sA,  sX1, g_hw0_hi, g_hw0_lo, warpRow, lane); // X2
    __syncwarp();
    warp_gemm<64, 64, 68, 68, true,  true >(sX1, sX3, g_hw1_hi, g_hw1_lo, warpRow, lane); // X3
    __syncwarp();
    warp_gemm<64,  8, 68, 12, false, true >(sX3, sA,  g_hw2_hi, g_hw2_lo, warpRow, lane); // X4
    __syncwarp();

    // epilogue: one thread per row
    int r = warpRow + lane;
    int gi = base + r;
    if (gi < N) {
        float h0 = sH2[r * 20];
        float s = expf(h0 - 1.f) * g_dts[gi];
        float c0 = sA[r * 12 + 0];
        float c1 = sA[r * 12 + 1];
        float c2 = sA[r * 12 + 2];
        g_samp[gi] = make_float4(1.f / (1.f + expf(-c0)),
                                 1.f / (1.f + expf(-c1)),
                                 1.f / (1.f + expf(-c2)), s);
    }
}

// ---------------------------------------------------------------------------
// Kernel C: warp per ray — scan of s, transmittance, weighted accumulation
// ---------------------------------------------------------------------------
__global__ __launch_bounds__(256)
void accum_kernel(const float* __restrict__ ts, const float* __restrict__ te,
                  const int* __restrict__ ridx, float* __restrict__ out,
                  int N, int R)
{
    const unsigned FULL = 0xFFFFFFFFu;
    int warp = (blockIdx.x * blockDim.x + threadIdx.x) >> 5;
    int lane = threadIdx.x & 31;
    if (warp >= R) return;
    int r = warp;

    int lo = 0, hi = N;
    while (lo < hi) { int m = (lo + hi) >> 1; if (ridx[m] < r) lo = m + 1; else hi = m; }
    int start = lo;
    hi = N;
    while (lo < hi) { int m = (lo + hi) >> 1; if (ridx[m] < r + 1) lo = m + 1; else hi = m; }
    int end = lo;

    float carry = 0.f;
    float cr = 0.f, cg = 0.f, cb = 0.f, cw = 0.f, cd = 0.f;

    for (int base = start; base < end; base += 32) {
        int i = base + lane;
        bool v = i < end;
        float4 q = v ? g_samp[i] : make_float4(0.f, 0.f, 0.f, 0.f);
        float si = q.w;
        float tm = v ? 0.5f * (ts[i] + te[i]) : 0.f;

        float incl = si;
#pragma unroll
        for (int off = 1; off < 32; off <<= 1) {
            float t = __shfl_up_sync(FULL, incl, off);
            if (lane >= off) incl += t;
        }
        float excl  = carry + (incl - si);
        float trans = expf(-excl);
        float alpha = 1.f - expf(-si);
        float wgt = trans * alpha;

        cr += wgt * q.x;
        cg += wgt * q.y;
        cb += wgt * q.z;
        cw += wgt;
        cd += wgt * tm;

        carry += __shfl_sync(FULL, incl, 31);
    }

#pragma unroll
    for (int off = 16; off >= 1; off >>= 1) {
        cr += __shfl_xor_sync(FULL, cr, off);
        cg += __shfl_xor_sync(FULL, cg, off);
        cb += __shfl_xor_sync(FULL, cb, off);
        cw += __shfl_xor_sync(FULL, cw, off);
        cd += __shfl_xor_sync(FULL, cd, off);
    }

    if (lane == 0) {
        out[3 * r + 0] = cr;
        out[3 * r + 1] = cg;
        out[3 * r + 2] = cb;
        out[3 * R + r] = cw;
        out[4 * R + r] = cd / fmaxf(cw, 1.1920929e-7f);
    }
}

// ---------------------------------------------------------------------------
extern "C" void kernel_launch(void* const* d_in, const int* in_sizes, int n_in,
                              void* d_out, int out_size)
{
    const float* ts     = (const float*)d_in[0];
    const float* te     = (const float*)d_in[1];
    const float* ro     = (const float*)d_in[2];
    const float* rd     = (const float*)d_in[3];
    const int*   ridx   = (const int*)  d_in[4];
    const float* tables = (const float*)d_in[5];
    const float* w0     = (const float*)d_in[6];
    const float* w1     = (const float*)d_in[7];
    const float* hw0    = (const float*)d_in[8];
    const float* hw1    = (const float*)d_in[9];
    const float* hw2    = (const float*)d_in[10];
    const float* aabb   = (const float*)d_in[11];
    float* out = (float*)d_out;

    int N = in_sizes[0];
    int R = in_sizes[2] / 3;

    ResTable res;
    double scale = exp((log(4096.0) - log(16.0)) / 15.0);
    double acc = 16.0;
    for (int l = 0; l < 16; l++) { res.r[l] = (float)floor(acc); acc *= scale; }

    static const size_t MLP_SMEM = 24576 * sizeof(float); // 98304 B
    cudaFuncSetAttribute(mlp_kernel, cudaFuncAttributeMaxDynamicSharedMemorySize,
                         (int)MLP_SMEM);

    prep_kernel<<<16, 256>>>(w0, w1, hw0, hw1, hw2);
    hash_kernel<<<(N + 255) / 256, 256>>>(ts, te, ro, rd, ridx, tables, aabb, res, N);
    mlp_kernel<<<(N + 127) / 128, 128, MLP_SMEM>>>(N);
    accum_kernel<<<(R * 32 + 255) / 256, 256>>>(ts, te, ridx, out, N, R);
}

// round 7
// speedup vs baseline: 2.2773x; 1.6317x over previous
#include <cuda_runtime.h>
#include <cuda_bf16.h>
#include <math.h>
#include <stdint.h>

#define NMAX   (1 << 19)
#define RMAX   8192
#define TBL    (1 << 19)
#define TMASK  (TBL - 1)

// ---------------- global scratch ----------------
__device__ unsigned g_encp[NMAX * 16];     // packed bf16x2 hash features (16 pairs)
__device__ float    g_dts [NMAX];          // (t1-t0)*selector
__device__ float4   g_samp[NMAX];          // {r,g,b,s}
__device__ float    g_raypart[RMAX * 64];  // SH(dir) @ hw0[0:16,:]  (fp32 exact)

// packed bf16 weights
__device__ unsigned g_Wp0  [16 * 64];      // base l0: K=32
__device__ unsigned g_Wp1  [32 * 16];      // base l1: K=64
__device__ unsigned g_Wpe  [ 8 * 64];      // head l0 emb part: K=16 (15+pad)
__device__ unsigned g_Wh1hi[32 * 64];      // head l1 hi
__device__ unsigned g_Wh1lo[32 * 64];      // head l1 lo
__device__ unsigned g_Wh2hi[32 *  8];      // head l2 hi (N=3 pad 8)
__device__ unsigned g_Wh2lo[32 *  8];      // head l2 lo

struct ResTable { float r[16]; };

__device__ __forceinline__ unsigned packbf(float lo, float hi) {
    unsigned r;
    asm("cvt.rn.bf16x2.f32 %0, %1, %2;" : "=r"(r) : "f"(hi), "f"(lo));
    return r;
}
__device__ __forceinline__ float bfround(float v) {
    return __bfloat162float(__float2bfloat16_rn(v));
}

// ---------------------------------------------------------------------------
// prep: pack weights to bf16 (hi/lo for head layers 1,2)
// ---------------------------------------------------------------------------
__global__ void prep_kernel(const float* __restrict__ w0, const float* __restrict__ w1,
                            const float* __restrict__ hw0, const float* __restrict__ hw1,
                            const float* __restrict__ hw2)
{
    int i = blockIdx.x * 256 + threadIdx.x;   // 0..2047
    if (i < 1024) {
        int kp = i >> 6, n = i & 63;
        g_Wp0[i] = packbf(w0[(2 * kp) * 64 + n], w0[(2 * kp + 1) * 64 + n]);
    }
    if (i < 512) {
        int kp = i >> 4, n = i & 15;
        g_Wp1[i] = packbf(w1[(2 * kp) * 16 + n], w1[(2 * kp + 1) * 16 + n]);
    }
    if (i < 512) {
        int kp = i >> 6, n = i & 63;
        int k0 = 16 + 2 * kp, k1 = k0 + 1;
        float v0 = hw0[k0 * 64 + n];
        float v1 = (k1 < 31) ? hw0[k1 * 64 + n] : 0.f;
        g_Wpe[i] = packbf(v0, v1);
    }
    if (i < 2048) {
        int kp = i >> 6, n = i & 63;
        float v0 = hw1[(2 * kp) * 64 + n], v1 = hw1[(2 * kp + 1) * 64 + n];
        float h0 = bfround(v0), h1 = bfround(v1);
        g_Wh1hi[i] = packbf(h0, h1);
        g_Wh1lo[i] = packbf(v0 - h0, v1 - h1);
    }
    if (i < 256) {
        int kp = i >> 3, n = i & 7;
        float v0 = (n < 3) ? hw2[(2 * kp) * 3 + n] : 0.f;
        float v1 = (n < 3) ? hw2[(2 * kp + 1) * 3 + n] : 0.f;
        float h0 = bfround(v0), h1 = bfround(v1);
        g_Wh2hi[kp * 8 + n] = packbf(h0, h1);
        g_Wh2lo[kp * 8 + n] = packbf(v0 - h0, v1 - h1);
    }
}

// ---------------------------------------------------------------------------
// per-ray SH @ hw0[0:16,:]  (fp32 exact)
// ---------------------------------------------------------------------------
__global__ void raypart_kernel(const float* __restrict__ rd,
                               const float* __restrict__ hw0, int R)
{
    int idx = blockIdx.x * 256 + threadIdx.x;
    if (idx >= R * 64) return;
    int r = idx >> 6, n = idx & 63;
    float x = rd[3 * r + 0], y = rd[3 * r + 1], z = rd[3 * r + 2];
    float x2 = x * x, y2 = y * y, z2 = z * z;
    float xy = x * y, yz = y * z, xz = x * z;
    float sh[16];
    sh[0]  = 0.28209479177387814f;
    sh[1]  = -0.48860251190291987f * y;
    sh[2]  =  0.48860251190291987f * z;
    sh[3]  = -0.48860251190291987f * x;
    sh[4]  =  1.0925484305920792f * xy;
    sh[5]  = -1.0925484305920792f * yz;
    sh[6]  =  0.94617469575756f * z2 - 0.31539156525252005f;
    sh[7]  = -1.0925484305920792f * xz;
    sh[8]  =  0.5462742152960396f * (x2 - y2);
    sh[9]  = -0.5900435899266435f * y * (3.f * x2 - y2);
    sh[10] =  2.890611442640554f * xy * z;
    sh[11] = -0.4570457994644658f * y * (4.f * z2 - x2 - y2);
    sh[12] =  0.3731763325901154f * z * (2.f * z2 - 3.f * x2 - 3.f * y2);
    sh[13] = -0.4570457994644658f * x * (4.f * z2 - x2 - y2);
    sh[14] =  1.445305721320277f * z * (x2 - y2);
    sh[15] = -0.5900435899266435f * x * (x2 - 3.f * y2);
    float acc = 0.f;
#pragma unroll
    for (int k = 0; k < 16; k++) acc = fmaf(sh[k], hw0[k * 64 + n], acc);
    g_raypart[r * 64 + n] = acc;
}

// ---------------------------------------------------------------------------
// hash encode: 2 threads per sample (8 levels each), packed bf16 output
// ---------------------------------------------------------------------------
__global__ __launch_bounds__(256)
void hash_kernel(
    const float* __restrict__ ts, const float* __restrict__ te,
    const float* __restrict__ ro, const float* __restrict__ rd,
    const int*   __restrict__ ridx,
    const float* __restrict__ tables,
    const float* __restrict__ aabb,
    ResTable res, int N)
{
    int t = blockIdx.x * 256 + threadIdx.x;
    int i = t >> 1, half = t & 1;
    if (i >= N) return;

    int r = ridx[i];
    float t0 = ts[i], t1 = te[i];
    float tmid = (t0 + t1) * 0.5f;

    float ox = ro[3 * r + 0], oy = ro[3 * r + 1], oz = ro[3 * r + 2];
    float dx = rd[3 * r + 0], dy = rd[3 * r + 1], dz = rd[3 * r + 2];

    float a0 = aabb[0], a1 = aabb[1], a2 = aabb[2];
    float a3 = aabb[3], a4 = aabb[4], a5 = aabb[5];

    float xn0 = (ox + dx * tmid - a0) / (a3 - a0 + 1e-5f);
    float xn1 = (oy + dy * tmid - a1) / (a4 - a1 + 1e-5f);
    float xn2 = (oz + dz * tmid - a2) / (a5 - a2 + 1e-5f);

    if (half == 0) {
        bool sel = (xn0 > 0.f) && (xn0 < 1.f) &&
                   (xn1 > 0.f) && (xn1 < 1.f) &&
                   (xn2 > 0.f) && (xn2 < 1.f);
        g_dts[i] = sel ? (t1 - t0) : 0.f;
    }

    float xc0 = fminf(fmaxf(xn0, 0.f), 1.f);
    float xc1 = fminf(fmaxf(xn1, 0.f), 1.f);
    float xc2 = fminf(fmaxf(xn2, 0.f), 1.f);

    const float2* __restrict__ tb = (const float2*)tables;
    unsigned e[8];
    const int lbase = half * 8;

#pragma unroll
    for (int ll = 0; ll < 8; ll++) {
        int l = lbase + ll;
        float rs = res.r[l];
        float px = xc0 * rs, py = xc1 * rs, pz = xc2 * rs;
        float p0x = floorf(px), p0y = floorf(py), p0z = floorf(pz);
        float fx = px - p0x, fy = py - p0y, fz = pz - p0z;
        unsigned ux = (unsigned)p0x, uy = (unsigned)p0y, uz = (unsigned)p0z;
        unsigned hx0 = ux,               hx1 = ux + 1u;
        unsigned hy0 = uy * 2654435761u, hy1 = (uy + 1u) * 2654435761u;
        unsigned hz0 = uz * 805459861u,  hz1 = (uz + 1u) * 805459861u;
        float wx0 = 1.f - fx, wy0 = 1.f - fy, wz0 = 1.f - fz;
        const float2* __restrict__ tp = tb + (size_t)l * TBL;
        float f0 = 0.f, f1 = 0.f;
#pragma unroll
        for (int c = 0; c < 8; c++) {
            unsigned h = ((c & 4) ? hx1 : hx0) ^ ((c & 2) ? hy1 : hy0) ^ ((c & 1) ? hz1 : hz0);
            h &= TMASK;
            float w = ((c & 4) ? fx : wx0) * ((c & 2) ? fy : wy0) * ((c & 1) ? fz : wz0);
            float2 v = __ldg(tp + h);
            f0 = fmaf(v.x, w, f0);
            f1 = fmaf(v.y, w, f1);
        }
        e[ll] = packbf(f0, f1);
    }

    uint4* __restrict__ out4 = (uint4*)g_encp;
    out4[(size_t)i * 4 + half * 2 + 0] = make_uint4(e[0], e[1], e[2], e[3]);
    out4[(size_t)i * 4 + half * 2 + 1] = make_uint4(e[4], e[5], e[6], e[7]);
}

// ---------------------------------------------------------------------------
// warp-level bf16 GEMM (mma.m16n8k16), warp owns 32 rows
// ---------------------------------------------------------------------------
__device__ __forceinline__ void mma16(float c[4], const unsigned a[4],
                                      unsigned b0, unsigned b1)
{
    asm volatile(
        "mma.sync.aligned.m16n8k16.row.col.f32.bf16.bf16.f32 "
        "{%0,%1,%2,%3}, {%4,%5,%6,%7}, {%8,%9}, {%0,%1,%2,%3};"
        : "+f"(c[0]), "+f"(c[1]), "+f"(c[2]), "+f"(c[3])
        : "r"(a[0]), "r"(a[1]), "r"(a[2]), "r"(a[3]), "r"(b0), "r"(b1));
}

template <int K, int NOUT, int SIN, int SOUT,
          bool RELU, bool SPLIT, bool RPINIT, bool OUTF32, bool SPLITOUT>
__device__ __forceinline__ void wgemm(
    const unsigned* __restrict__ sInHi, const unsigned* __restrict__ sInLo,
    unsigned* __restrict__ outHi, unsigned* __restrict__ outLo,
    float* __restrict__ outF,
    const unsigned* __restrict__ Whi, const unsigned* __restrict__ Wlo,
    const float* __restrict__ rayPart, const int* __restrict__ sRid,
    int warpRow, int lane)
{
    const int g = lane >> 2, c = lane & 3;
    const int KS = K / 16;
#pragma unroll
    for (int mi = 0; mi < 2; mi++) {
        const int r0 = warpRow + mi * 16;
        unsigned aHi[KS][4], aLo[KS][4];
#pragma unroll
        for (int ks = 0; ks < KS; ks++) {
            aHi[ks][0] = sInHi[(r0 + g    ) * SIN + ks * 8 + c];
            aHi[ks][1] = sInHi[(r0 + g + 8) * SIN + ks * 8 + c];
            aHi[ks][2] = sInHi[(r0 + g    ) * SIN + ks * 8 + c + 4];
            aHi[ks][3] = sInHi[(r0 + g + 8) * SIN + ks * 8 + c + 4];
            if (SPLIT) {
                aLo[ks][0] = sInLo[(r0 + g    ) * SIN + ks * 8 + c];
                aLo[ks][1] = sInLo[(r0 + g + 8) * SIN + ks * 8 + c];
                aLo[ks][2] = sInLo[(r0 + g    ) * SIN + ks * 8 + c + 4];
                aLo[ks][3] = sInLo[(r0 + g + 8) * SIN + ks * 8 + c + 4];
            }
        }
        int ridA = 0, ridB = 0;
        if (RPINIT) { ridA = sRid[r0 + g]; ridB = sRid[r0 + g + 8]; }
#pragma unroll
        for (int ni = 0; ni < NOUT / 8; ni++) {
            float acc[4];
            if (RPINIT) {
                float2 pa = __ldg((const float2*)(rayPart + ridA * 64 + ni * 8 + 2 * c));
                float2 pb = __ldg((const float2*)(rayPart + ridB * 64 + ni * 8 + 2 * c));
                acc[0] = pa.x; acc[1] = pa.y; acc[2] = pb.x; acc[3] = pb.y;
            } else {
                acc[0] = acc[1] = acc[2] = acc[3] = 0.f;
            }
#pragma unroll
            for (int ks = 0; ks < KS; ks++) {
                unsigned bh0 = __ldg(Whi + (ks * 8 + c    ) * NOUT + ni * 8 + g);
                unsigned bh1 = __ldg(Whi + (ks * 8 + c + 4) * NOUT + ni * 8 + g);
                mma16(acc, aHi[ks], bh0, bh1);
                if (SPLIT) {
                    mma16(acc, aLo[ks], bh0, bh1);
                    unsigned bl0 = __ldg(Wlo + (ks * 8 + c    ) * NOUT + ni * 8 + g);
                    unsigned bl1 = __ldg(Wlo + (ks * 8 + c + 4) * NOUT + ni * 8 + g);
                    mma16(acc, aHi[ks], bl0, bl1);
                }
            }
            if (RELU) {
                acc[0] = fmaxf(acc[0], 0.f); acc[1] = fmaxf(acc[1], 0.f);
                acc[2] = fmaxf(acc[2], 0.f); acc[3] = fmaxf(acc[3], 0.f);
            }
            if (OUTF32) {
                float* oA = outF + (r0 + g    ) * SOUT + ni * 8 + 2 * c;
                float* oB = outF + (r0 + g + 8) * SOUT + ni * 8 + 2 * c;
                oA[0] = acc[0]; oA[1] = acc[1];
                oB[0] = acc[2]; oB[1] = acc[3];
            } else {
                outHi[(r0 + g    ) * SOUT + ni * 4 + c] = packbf(acc[0], acc[1]);
                outHi[(r0 + g + 8) * SOUT + ni * 4 + c] = packbf(acc[2], acc[3]);
                if (SPLITOUT) {
                    float h0 = bfround(acc[0]), h1 = bfround(acc[1]);
                    float h2 = bfround(acc[2]), h3 = bfround(acc[3]);
                    outLo[(r0 + g    ) * SOUT + ni * 4 + c] = packbf(acc[0] - h0, acc[1] - h1);
                    outLo[(r0 + g + 8) * SOUT + ni * 4 + c] = packbf(acc[2] - h2, acc[3] - h3);
                }
            }
        }
    }
}

// ---------------------------------------------------------------------------
// MLP chain: 128 samples / block, 4 warps, warp-private rows.
// NOTE: buffer ALIASING is block-global (strides differ), so stages are
// separated by __syncthreads(), not __syncwarp() — this was the R5 race.
// ---------------------------------------------------------------------------
#define ENC_OFF   0        // stride 17, 2176        (aliased: X2)
#define X2HI_OFF  0        // stride 33, 4224
#define X2LO_OFF  4224     // stride 33, 4224
#define X1_OFF    8448     // stride 33, 4224        (aliased: X4)
#define X4_OFF    8448     // f32 stride 9, 1152
#define H2_OFF    12672    // f32 stride 17, 2176    (aliased: X3)
#define X3HI_OFF  12672    // stride 33, 4224
#define X3LO_OFF  16896    // stride 33, 4224
#define EMB_OFF   21120    // stride 9, 1152
#define SIG_OFF   22272    // f32, 128
#define RID_OFF   22400    // int, 128
#define SMEM_U32  22528    // 90112 bytes

__global__ __launch_bounds__(128)
void mlp_kernel(const int* __restrict__ ridx, int N)
{
    extern __shared__ unsigned smu[];
    float* smf = (float*)smu;
    int*   smi = (int*)smu;

    const int lane = threadIdx.x & 31;
    const int w = threadIdx.x >> 5;
    const int warpRow = w * 32;
    const int base = blockIdx.x * 128;

    // load enc (packed bf16 pairs) + ray ids, warp-private rows
    {
        const uint4* ev = (const uint4*)g_encp;
        for (int t = lane; t < 128; t += 32) {
            int r = warpRow + (t >> 2), q = t & 3;
            int gi = base + r;
            uint4 v = (gi < N) ? __ldg(ev + (size_t)gi * 4 + q)
                               : make_uint4(0u, 0u, 0u, 0u);
            unsigned* dst = smu + ENC_OFF + r * 17 + q * 4;
            dst[0] = v.x; dst[1] = v.y; dst[2] = v.z; dst[3] = v.w;
        }
        int r = warpRow + lane;
        int gi = base + r;
        smi[RID_OFF + r] = (gi < N) ? __ldg(ridx + gi) : 0;
    }
    __syncthreads();

    // X1 = relu(enc @ w0)           single bf16
    wgemm<32, 64, 17, 33, true, false, false, false, false>(
        smu + ENC_OFF, nullptr, smu + X1_OFF, nullptr, nullptr,
        g_Wp0, nullptr, nullptr, nullptr, warpRow, lane);
    __syncthreads();

    // H2 = X1 @ w1  (f32 out)       single bf16
    wgemm<64, 16, 33, 17, false, false, false, true, false>(
        smu + X1_OFF, nullptr, nullptr, nullptr, smf + H2_OFF,
        g_Wp1, nullptr, nullptr, nullptr, warpRow, lane);
    __syncthreads();

    // repack: sig = H2[0]; emb pairs = (H2[1],H2[2]),...,(H2[15],0)
    {
        int r = warpRow + lane;
        const float* hrow = smf + H2_OFF + r * 17;
        smf[SIG_OFF + r] = hrow[0];
        unsigned* erow = smu + EMB_OFF + r * 9;
#pragma unroll
        for (int kp = 0; kp < 8; kp++) {
            float v0 = hrow[1 + 2 * kp];
            float v1 = (kp < 7) ? hrow[2 + 2 * kp] : 0.f;
            erow[kp] = packbf(v0, v1);
        }
    }
    __syncthreads();

    // X2 = relu(raypart[rid] + emb @ Wpe)   acc-init from fp32 raypart
    // (writes X2 over ENC region — safe: ENC fully consumed at stage 1)
    wgemm<16, 64, 9, 33, true, false, true, false, true>(
        smu + EMB_OFF, nullptr, smu + X2HI_OFF, smu + X2LO_OFF, nullptr,
        g_Wpe, nullptr, g_raypart, smi + RID_OFF, warpRow, lane);
    __syncthreads();

    // X3 = relu(X2 @ hw1)   bf16x3   (writes over H2 region — consumed at repack)
    wgemm<64, 64, 33, 33, true, true, false, false, true>(
        smu + X2HI_OFF, smu + X2LO_OFF, smu + X3HI_OFF, smu + X3LO_OFF, nullptr,
        g_Wh1hi, g_Wh1lo, nullptr, nullptr, warpRow, lane);
    __syncthreads();

    // X4 = X3 @ hw2  (f32 out)  bf16x3  (writes over X1 region — consumed at stage 2)
    wgemm<64, 8, 33, 9, false, true, false, true, false>(
        smu + X3HI_OFF, smu + X3LO_OFF, nullptr, nullptr, smf + X4_OFF,
        g_Wh2hi, g_Wh2lo, nullptr, nullptr, warpRow, lane);
    __syncthreads();

    // epilogue
    {
        int r = warpRow + lane;
        int gi = base + r;
        if (gi < N) {
            float h0 = smf[SIG_OFF + r];
            float s = expf(h0 - 1.f) * __ldg(g_dts + gi);
            float c0 = smf[X4_OFF + r * 9 + 0];
            float c1 = smf[X4_OFF + r * 9 + 1];
            float c2 = smf[X4_OFF + r * 9 + 2];
            g_samp[gi] = make_float4(1.f / (1.f + expf(-c0)),
                                     1.f / (1.f + expf(-c1)),
                                     1.f / (1.f + expf(-c2)), s);
        }
    }
}

// ---------------------------------------------------------------------------
// accumulation: warp per ray
// ---------------------------------------------------------------------------
__global__ __launch_bounds__(256)
void accum_kernel(const float* __restrict__ ts, const float* __restrict__ te,
                  const int* __restrict__ ridx, float* __restrict__ out,
                  int N, int R)
{
    const unsigned FULL = 0xFFFFFFFFu;
    int warp = (blockIdx.x * blockDim.x + threadIdx.x) >> 5;
    int lane = threadIdx.x & 31;
    if (warp >= R) return;
    int r = warp;

    int lo = 0, hi = N;
    while (lo < hi) { int m = (lo + hi) >> 1; if (ridx[m] < r) lo = m + 1; else hi = m; }
    int start = lo;
    hi = N;
    while (lo < hi) { int m = (lo + hi) >> 1; if (ridx[m] < r + 1) lo = m + 1; else hi = m; }
    int end = lo;

    float carry = 0.f;
    float cr = 0.f, cg = 0.f, cb = 0.f, cw = 0.f, cd = 0.f;

    for (int base = start; base < end; base += 32) {
        int i = base + lane;
        bool v = i < end;
        float4 q = v ? g_samp[i] : make_float4(0.f, 0.f, 0.f, 0.f);
        float si = q.w;
        float tm = v ? 0.5f * (ts[i] + te[i]) : 0.f;

        float incl = si;
#pragma unroll
        for (int off = 1; off < 32; off <<= 1) {
            float t = __shfl_up_sync(FULL, incl, off);
            if (lane >= off) incl += t;
        }
        float excl  = carry + (incl - si);
        float trans = expf(-excl);
        float alpha = 1.f - expf(-si);
        float wgt = trans * alpha;

        cr += wgt * q.x;
        cg += wgt * q.y;
        cb += wgt * q.z;
        cw += wgt;
        cd += wgt * tm;

        carry += __shfl_sync(FULL, incl, 31);
    }

#pragma unroll
    for (int off = 16; off >= 1; off >>= 1) {
        cr += __shfl_xor_sync(FULL, cr, off);
        cg += __shfl_xor_sync(FULL, cg, off);
        cb += __shfl_xor_sync(FULL, cb, off);
        cw += __shfl_xor_sync(FULL, cw, off);
        cd += __shfl_xor_sync(FULL, cd, off);
    }

    if (lane == 0) {
        out[3 * r + 0] = cr;
        out[3 * r + 1] = cg;
        out[3 * r + 2] = cb;
        out[3 * R + r] = cw;
        out[4 * R + r] = cd / fmaxf(cw, 1.1920929e-7f);
    }
}

// ---------------------------------------------------------------------------
extern "C" void kernel_launch(void* const* d_in, const int* in_sizes, int n_in,
                              void* d_out, int out_size)
{
    const float* ts     = (const float*)d_in[0];
    const float* te     = (const float*)d_in[1];
    const float* ro     = (const float*)d_in[2];
    const float* rd     = (const float*)d_in[3];
    const int*   ridx   = (const int*)  d_in[4];
    const float* tables = (const float*)d_in[5];
    const float* w0     = (const float*)d_in[6];
    const float* w1     = (const float*)d_in[7];
    const float* hw0    = (const float*)d_in[8];
    const float* hw1    = (const float*)d_in[9];
    const float* hw2    = (const float*)d_in[10];
    const float* aabb   = (const float*)d_in[11];
    float* out = (float*)d_out;

    int N = in_sizes[0];
    int R = in_sizes[2] / 3;

    ResTable res;
    double scale = exp((log(4096.0) - log(16.0)) / 15.0);
    double acc = 16.0;
    for (int l = 0; l < 16; l++) { res.r[l] = (float)floor(acc); acc *= scale; }

    cudaFuncSetAttribute(mlp_kernel, cudaFuncAttributeMaxDynamicSharedMemorySize,
                         SMEM_U32 * 4);

    prep_kernel<<<8, 256>>>(w0, w1, hw0, hw1, hw2);
    raypart_kernel<<<(R * 64 + 255) / 256, 256>>>(rd, hw0, R);
    hash_kernel<<<(2 * N + 255) / 256, 256>>>(ts, te, ro, rd, ridx, tables, aabb, res, N);
    mlp_kernel<<<(N + 127) / 128, 128, SMEM_U32 * 4>>>(ridx, N);
    accum_kernel<<<(R * 32 + 255) / 256, 256>>>(ts, te, ridx, out, N, R);
}